// round 1
// baseline (speedup 1.0000x reference)
#include <cuda_runtime.h>

// Problem constants
#define NB   32
#define NT   4096
#define NF   1024     // F_IN
#define NH   16
#define NDEP 64
#define NDM  1024     // D

// ---------------- scratch (device globals; no allocation) ----------------
__device__ float g_qpart[8 * NB * NDM];          // q GEMV k-split partials
__device__ float g_q[NB * NDM];                  // q = state@Wq + bq
__device__ float g_p[NB * NF * NH];              // p[b][f][h], scaled by 1/8
__device__ float g_L[NB * NH * NT];              // logits -> attn (in place)
__device__ float g_wp[NB * 8 * NH * NF];         // pass2 t-chunk partials
__device__ float g_w[NB * NH * NF];              // w[b][h][f]
__device__ float g_op[8 * NB * NDM];             // out f-split partials
__device__ float g_out[NB * NDM];                // out + bv
__device__ float g_fpart[8 * NB * NDM];          // final GEMV partials

// ---------------- f32x2 packed helpers ----------------
__device__ __forceinline__ unsigned long long pk2(float lo, float hi) {
    unsigned long long r;
    asm("mov.b64 %0, {%1, %2};" : "=l"(r) : "f"(lo), "f"(hi));
    return r;
}
__device__ __forceinline__ unsigned long long ffma2(unsigned long long a,
                                                    unsigned long long b,
                                                    unsigned long long c) {
    unsigned long long d;
    asm("fma.rn.f32x2 %0, %1, %2, %3;" : "=l"(d) : "l"(a), "l"(b), "l"(c));
    return d;
}
__device__ __forceinline__ void upk2(unsigned long long v, float& lo, float& hi) {
    asm("mov.b64 {%0, %1}, %2;" : "=f"(lo), "=f"(hi) : "l"(v));
}

// ---------------- generic 32-batch GEMV, k-split partials ----------------
// part[kc][b][j] = sum_{k in chunk kc} X[b][k] * W[k][j]
// grid (8 j-tiles, 8 k-chunks), 128 threads
__global__ void gemv_part_kernel(const float* __restrict__ X,
                                 const float* __restrict__ W,
                                 float* __restrict__ part) {
    __shared__ float xs[32][128];
    const int jt = blockIdx.x, kc = blockIdx.y, tid = threadIdx.x;
    for (int i = tid; i < 32 * 128; i += 128) {
        int bb = i >> 7, kl = i & 127;
        xs[bb][kl] = X[bb * NDM + kc * 128 + kl];
    }
    __syncthreads();
    const int j = jt * 128 + tid;
    float acc[32];
#pragma unroll
    for (int bb = 0; bb < 32; bb++) acc[bb] = 0.f;
    for (int kl = 0; kl < 128; kl++) {
        float wv = W[(kc * 128 + kl) * NDM + j];
#pragma unroll
        for (int bb = 0; bb < 32; bb++) acc[bb] += xs[bb][kl] * wv;
    }
#pragma unroll
    for (int bb = 0; bb < 32; bb++) part[(kc * 32 + bb) * NDM + j] = acc[bb];
}

// out[i] = bias[i%1024] + sum_{c<8} part[c][i];  n = 32768, grid 128 x 256
__global__ void combine_kernel(const float* __restrict__ part,
                               const float* __restrict__ bias,
                               float* __restrict__ out) {
    int i = blockIdx.x * 256 + threadIdx.x;
    float s = bias[i & (NDM - 1)];
#pragma unroll
    for (int c = 0; c < 8; c++) s += part[c * (32 * NDM) + i];
    out[i] = s;
}

// ---------------- p[b][f][h] = (1/8) sum_d Wv[f][h*64+d] * q[b][h*64+d] ----
// grid (64 f-tiles, 4 b-groups), 256 threads: h = tid>>4 (warp-uniform-ish), fl = tid&15
__global__ void pcalc_kernel(const float* __restrict__ Wv) {
    __shared__ float qs[8][NDM];
    const int ft = blockIdx.x, bg = blockIdx.y, tid = threadIdx.x;
    for (int i = tid; i < 8 * NDM; i += 256)
        qs[i >> 10][i & 1023] = g_q[(bg * 8 + (i >> 10)) * NDM + (i & 1023)];
    __syncthreads();
    const int h = tid >> 4, fl = tid & 15;
    const int f = ft * 16 + fl;
    float acc[8];
#pragma unroll
    for (int bb = 0; bb < 8; bb++) acc[bb] = 0.f;
    for (int d = 0; d < NDEP; d++) {
        float wv = Wv[f * NDM + h * NDEP + d];
#pragma unroll
        for (int bb = 0; bb < 8; bb++) acc[bb] += wv * qs[bb][h * NDEP + d];
    }
#pragma unroll
    for (int bb = 0; bb < 8; bb++)
        g_p[((bg * 8 + bb) * NF + f) * NH + h] = acc[bb] * 0.125f;
}

// ---------------- pass1: L[b][h][t] = F[b][t][:] . p[b][:][h] ----------------
// grid (8 t-tiles of 512, 32 b), 128 threads; thread tile 8 rows x 8 heads; f32x2
__global__ __launch_bounds__(128) void pass1_kernel(const float* __restrict__ F) {
    __shared__ __align__(16) float Fs[16 * 516];   // [k][row], pad 4
    __shared__ __align__(16) float ps[16][16];     // [k][h]
    const int b = blockIdx.y, t0 = blockIdx.x * 512;
    const int tid = threadIdx.x;
    const int hg = tid >> 6, rg = tid & 63;
    const int r0 = rg * 8, h0 = hg * 8;
    const float* Fbase = F + (b * NT + t0) * NF;

    unsigned long long acc[8][4];
#pragma unroll
    for (int h = 0; h < 8; h++)
#pragma unroll
        for (int r = 0; r < 4; r++) acc[h][r] = 0ull;

    for (int kc = 0; kc < 64; kc++) {
        const int k0 = kc * 16;
        __syncthreads();
        // load 512 rows x 16 k (64B aligned segments, fully-used sectors)
#pragma unroll
        for (int it = 0; it < 16; it++) {
            int v = tid + 128 * it;          // 0..2047
            int row = v >> 2, qd = (v & 3) * 4;
            float4 d4 = *(const float4*)(Fbase + row * NF + k0 + qd);
            Fs[(qd + 0) * 516 + row] = d4.x;
            Fs[(qd + 1) * 516 + row] = d4.y;
            Fs[(qd + 2) * 516 + row] = d4.z;
            Fs[(qd + 3) * 516 + row] = d4.w;
        }
        {
            const float* pb = g_p + (b * NF + k0) * NH;
            ((float2*)&ps[0][0])[tid] = ((const float2*)pb)[tid];
        }
        __syncthreads();
#pragma unroll
        for (int kk = 0; kk < 16; kk++) {
            float4 fa = *(const float4*)&Fs[kk * 516 + r0];
            float4 fb = *(const float4*)&Fs[kk * 516 + r0 + 4];
            unsigned long long F2[4];
            F2[0] = pk2(fa.x, fa.y); F2[1] = pk2(fa.z, fa.w);
            F2[2] = pk2(fb.x, fb.y); F2[3] = pk2(fb.z, fb.w);
#pragma unroll
            for (int h = 0; h < 8; h++) {
                float pv = ps[kk][h0 + h];
                unsigned long long p2 = pk2(pv, pv);
                acc[h][0] = ffma2(F2[0], p2, acc[h][0]);
                acc[h][1] = ffma2(F2[1], p2, acc[h][1]);
                acc[h][2] = ffma2(F2[2], p2, acc[h][2]);
                acc[h][3] = ffma2(F2[3], p2, acc[h][3]);
            }
        }
    }
#pragma unroll
    for (int h = 0; h < 8; h++) {
        float o[8];
#pragma unroll
        for (int r = 0; r < 4; r++) upk2(acc[h][r], o[2 * r], o[2 * r + 1]);
        float* Lp = g_L + (b * NH + h0 + h) * NT + t0 + r0;
        *(float4*)Lp       = make_float4(o[0], o[1], o[2], o[3]);
        *(float4*)(Lp + 4) = make_float4(o[4], o[5], o[6], o[7]);
    }
}

// ---------------- softmax over t per (b,h), in place on g_L ----------------
__global__ void softmax_kernel() {
    __shared__ float xs[NT];
    __shared__ float red[256];
    const int bh = blockIdx.x, tid = threadIdx.x;
    float* Lp = g_L + bh * NT;
    float lmax = -1e30f;
    for (int i = tid; i < NT; i += 256) {
        float v = Lp[i];
        xs[i] = v;
        lmax = fmaxf(lmax, v);
    }
    red[tid] = lmax;
    __syncthreads();
    for (int s = 128; s > 0; s >>= 1) {
        if (tid < s) red[tid] = fmaxf(red[tid], red[tid + s]);
        __syncthreads();
    }
    float m = red[0];
    __syncthreads();
    float lsum = 0.f;
    for (int i = tid; i < NT; i += 256) {
        float e = __expf(xs[i] - m);
        xs[i] = e;
        lsum += e;
    }
    red[tid] = lsum;
    __syncthreads();
    for (int s = 128; s > 0; s >>= 1) {
        if (tid < s) red[tid] += red[tid + s];
        __syncthreads();
    }
    float inv = 1.f / red[0];
    for (int i = tid; i < NT; i += 256) Lp[i] = xs[i] * inv;
}

// ---------------- pass2: wp[b][c][h][f] = sum_{t in chunk c} A[b][h][t]*F[b][t][f]
// grid (8 t-chunks of 512, 32 b), 256 threads; thread tile 8 heads x 8 f; f32x2
__global__ __launch_bounds__(256) void pass2_kernel(const float* __restrict__ F) {
    __shared__ __align__(16) float Fs[8 * NF];   // [t][f]
    __shared__ float As[8][16];                  // [t][h]
    const int b = blockIdx.y, c = blockIdx.x;
    const int tb = c * 512;
    const int tid = threadIdx.x;
    const int hg = tid >> 7, fg = tid & 127;
    const int f0 = fg * 8, h0 = hg * 8;

    unsigned long long acc[8][4];
#pragma unroll
    for (int h = 0; h < 8; h++)
#pragma unroll
        for (int r = 0; r < 4; r++) acc[h][r] = 0ull;

    for (int kc = 0; kc < 64; kc++) {
        const int t0 = tb + kc * 8;
        __syncthreads();
#pragma unroll
        for (int it = 0; it < 8; it++) {
            int v = tid + 256 * it;          // 0..2047
            int row = v >> 8, cq = (v & 255) * 4;
            *(float4*)&Fs[row * NF + cq] =
                *(const float4*)(F + (b * NT + t0 + row) * NF + cq);
        }
        if (tid < 128) {
            int hh = tid >> 3, kk = tid & 7;
            As[kk][hh] = g_L[(b * NH + hh) * NT + t0 + kk];
        }
        __syncthreads();
#pragma unroll
        for (int kk = 0; kk < 8; kk++) {
            float4 fa = *(const float4*)&Fs[kk * NF + f0];
            float4 fb = *(const float4*)&Fs[kk * NF + f0 + 4];
            unsigned long long F2[4];
            F2[0] = pk2(fa.x, fa.y); F2[1] = pk2(fa.z, fa.w);
            F2[2] = pk2(fb.x, fb.y); F2[3] = pk2(fb.z, fb.w);
#pragma unroll
            for (int h = 0; h < 8; h++) {
                float av = As[kk][h0 + h];
                unsigned long long a2 = pk2(av, av);
                acc[h][0] = ffma2(F2[0], a2, acc[h][0]);
                acc[h][1] = ffma2(F2[1], a2, acc[h][1]);
                acc[h][2] = ffma2(F2[2], a2, acc[h][2]);
                acc[h][3] = ffma2(F2[3], a2, acc[h][3]);
            }
        }
    }
#pragma unroll
    for (int h = 0; h < 8; h++) {
        float o[8];
#pragma unroll
        for (int r = 0; r < 4; r++) upk2(acc[h][r], o[2 * r], o[2 * r + 1]);
        float* wpp = g_wp + ((b * 8 + c) * NH + h0 + h) * NF + f0;
        *(float4*)wpp       = make_float4(o[0], o[1], o[2], o[3]);
        *(float4*)(wpp + 4) = make_float4(o[4], o[5], o[6], o[7]);
    }
}

// w[b][h][f] = sum_c wp[b][c][h][f];  n = 524288, grid 2048 x 256
__global__ void combine_w_kernel() {
    int i = blockIdx.x * 256 + threadIdx.x;
    int b = i >> 14, hf = i & 16383;
    float s = 0.f;
#pragma unroll
    for (int c = 0; c < 8; c++) s += g_wp[(b * 8 + c) * (NH * NF) + hf];
    g_w[i] = s;
}

// op[fc][b][j] = sum_{f in chunk} w[b][j/64][f] * Wv[f][j]
// grid (8 j-tiles, 8 f-chunks), 128 threads
__global__ void outpart_kernel(const float* __restrict__ Wv) {
    __shared__ float ws[32][2][128];
    const int jt = blockIdx.x, fc = blockIdx.y, tid = threadIdx.x;
    for (int i = tid; i < 32 * 2 * 128; i += 128) {
        int bb = i >> 8, hl = (i >> 7) & 1, fl = i & 127;
        ws[bb][hl][fl] = g_w[(bb * NH + jt * 2 + hl) * NF + fc * 128 + fl];
    }
    __syncthreads();
    const int j = jt * 128 + tid;
    const int hl = tid >> 6;
    float acc[32];
#pragma unroll
    for (int bb = 0; bb < 32; bb++) acc[bb] = 0.f;
    for (int fl = 0; fl < 128; fl++) {
        float wvv = Wv[(fc * 128 + fl) * NDM + j];
#pragma unroll
        for (int bb = 0; bb < 32; bb++) acc[bb] += ws[bb][hl][fl] * wvv;
    }
#pragma unroll
    for (int bb = 0; bb < 32; bb++) g_op[(fc * 32 + bb) * NDM + j] = acc[bb];
}

// ---------------- host launcher ----------------
extern "C" void kernel_launch(void* const* d_in, const int* in_sizes, int n_in,
                              void* d_out, int out_size) {
    const float* features = (const float*)d_in[0];
    const float* state    = (const float*)d_in[1];
    const float* Wq       = (const float*)d_in[2];
    const float* bq       = (const float*)d_in[3];
    const float* Wv       = (const float*)d_in[4];
    const float* bv       = (const float*)d_in[5];
    const float* Wd       = (const float*)d_in[6];
    const float* bd       = (const float*)d_in[7];
    float* out = (float*)d_out;

    void *p_qpart, *p_q, *p_op, *p_out, *p_fpart;
    cudaGetSymbolAddress(&p_qpart, g_qpart);
    cudaGetSymbolAddress(&p_q, g_q);
    cudaGetSymbolAddress(&p_op, g_op);
    cudaGetSymbolAddress(&p_out, g_out);
    cudaGetSymbolAddress(&p_fpart, g_fpart);

    // q = state @ Wq + bq
    gemv_part_kernel<<<dim3(8, 8), 128>>>(state, Wq, (float*)p_qpart);
    combine_kernel<<<128, 256>>>((const float*)p_qpart, bq, (float*)p_q);
    // p[b][f][h] (logit projection, scaled 1/8)
    pcalc_kernel<<<dim3(64, 4), 256>>>(Wv);
    // logits
    pass1_kernel<<<dim3(8, 32), 128>>>(features);
    // softmax (in place -> attention weights)
    softmax_kernel<<<NB * NH, 256>>>();
    // w = attn @ features (t-chunk partials, then reduce)
    pass2_kernel<<<dim3(8, 32), 256>>>(features);
    combine_w_kernel<<<2048, 256>>>();
    // out = w @ Wv + bv
    outpart_kernel<<<dim3(8, 8), 128>>>(Wv);
    combine_kernel<<<128, 256>>>((const float*)p_op, bv, (float*)p_out);
    // final = out @ Wd + bd
    gemv_part_kernel<<<dim3(8, 8), 128>>>((const float*)p_out, Wd, (float*)p_fpart);
    combine_kernel<<<128, 256>>>((const float*)p_fpart, bd, out);
    (void)in_sizes; (void)n_in; (void)out_size;
}

// round 2
// speedup vs baseline: 1.0799x; 1.0799x over previous
#include <cuda_runtime.h>

// Problem constants
#define NB   32
#define NT   4096
#define NF   1024     // F_IN
#define NH   16
#define NDEP 64
#define NDM  1024     // D

// ---------------- scratch (device globals; no allocation) ----------------
__device__ float g_qpart[16 * NB * NDM];         // q GEMV k-split partials
__device__ float g_q[NB * NDM];                  // q = state@Wq + bq
__device__ float g_p[NB * NF * NH];              // p[b][f][h], scaled by 1/8
__device__ float g_L[NB * NH * NT];              // logits -> attn (in place)
__device__ float g_wp[NB * 8 * NH * NF];         // pass2 t-chunk partials
__device__ float g_w[NB * NH * NF];              // w[b][h][f]
__device__ float g_op[16 * NB * NDM];            // out f-split partials
__device__ float g_out[NB * NDM];                // out + bv
__device__ float g_fpart[16 * NB * NDM];         // final GEMV partials

// ---------------- f32x2 packed helpers ----------------
__device__ __forceinline__ unsigned long long pk2(float lo, float hi) {
    unsigned long long r;
    asm("mov.b64 %0, {%1, %2};" : "=l"(r) : "f"(lo), "f"(hi));
    return r;
}
__device__ __forceinline__ unsigned long long ffma2(unsigned long long a,
                                                    unsigned long long b,
                                                    unsigned long long c) {
    unsigned long long d;
    asm("fma.rn.f32x2 %0, %1, %2, %3;" : "=l"(d) : "l"(a), "l"(b), "l"(c));
    return d;
}
__device__ __forceinline__ void upk2(unsigned long long v, float& lo, float& hi) {
    asm("mov.b64 {%0, %1}, %2;" : "=f"(lo), "=f"(hi) : "l"(v));
}

// ---------------- generic 32-batch GEMV, 16-way k-split partials ----------
// part[kc][b][j] = sum_{k in 64-chunk kc} X[b][k] * W[k][j]
// grid (8 j-tiles, 16 k-chunks), 128 threads
__global__ void gemv_part_kernel(const float* __restrict__ X,
                                 const float* __restrict__ W,
                                 float* __restrict__ part) {
    __shared__ float xs[32][64];
    const int jt = blockIdx.x, kc = blockIdx.y, tid = threadIdx.x;
    for (int i = tid; i < 32 * 64; i += 128) {
        int bb = i >> 6, kl = i & 63;
        xs[bb][kl] = X[bb * NDM + kc * 64 + kl];
    }
    __syncthreads();
    const int j = jt * 128 + tid;
    float acc[32];
#pragma unroll
    for (int bb = 0; bb < 32; bb++) acc[bb] = 0.f;
    for (int kl = 0; kl < 64; kl++) {
        float wv = W[(kc * 64 + kl) * NDM + j];
#pragma unroll
        for (int bb = 0; bb < 32; bb++) acc[bb] += xs[bb][kl] * wv;
    }
#pragma unroll
    for (int bb = 0; bb < 32; bb++) part[(kc * 32 + bb) * NDM + j] = acc[bb];
}

// out[i] = bias[i%1024] + sum_{c<16} part[c][i];  n = 32768, grid 128 x 256
__global__ void combine_kernel(const float* __restrict__ part,
                               const float* __restrict__ bias,
                               float* __restrict__ out) {
    int i = blockIdx.x * 256 + threadIdx.x;
    float s = bias[i & (NDM - 1)];
#pragma unroll
    for (int c = 0; c < 16; c++) s += part[c * (32 * NDM) + i];
    out[i] = s;
}

// ---------------- p[b][f][h] = (1/8) sum_d Wv[f][h*64+d] * q[b][h*64+d] ----
// grid (64 f-tiles, 4 b-groups), 256 threads
__global__ void pcalc_kernel(const float* __restrict__ Wv) {
    __shared__ float qs[8][NDM];
    const int ft = blockIdx.x, bg = blockIdx.y, tid = threadIdx.x;
    for (int i = tid; i < 8 * NDM; i += 256)
        qs[i >> 10][i & 1023] = g_q[(bg * 8 + (i >> 10)) * NDM + (i & 1023)];
    __syncthreads();
    const int h = tid >> 4, fl = tid & 15;
    const int f = ft * 16 + fl;
    float acc[8];
#pragma unroll
    for (int bb = 0; bb < 8; bb++) acc[bb] = 0.f;
    for (int d = 0; d < NDEP; d++) {
        float wv = Wv[f * NDM + h * NDEP + d];
#pragma unroll
        for (int bb = 0; bb < 8; bb++) acc[bb] += wv * qs[bb][h * NDEP + d];
    }
#pragma unroll
    for (int bb = 0; bb < 8; bb++)
        g_p[((bg * 8 + bb) * NF + f) * NH + h] = acc[bb] * 0.125f;
}

// ---------------- pass1: L[b][h][t] = F[b][t][:] . p[b][:][h] ----------------
// grid (8 t-tiles of 512, 32 b), 256 threads; thread tile 8 rows x 4 heads; f32x2
__global__ __launch_bounds__(256) void pass1_kernel(const float* __restrict__ F) {
    __shared__ __align__(16) float Fs[16 * 516];   // [k][row], pad 4
    __shared__ __align__(16) float ps[16][16];     // [k][h]
    const int b = blockIdx.y, t0 = blockIdx.x * 512;
    const int tid = threadIdx.x;
    const int hg = tid >> 6, rg = tid & 63;
    const int r0 = rg * 8, h0 = hg * 4;
    const float* Fbase = F + (b * NT + t0) * NF;

    unsigned long long acc[4][4];
#pragma unroll
    for (int h = 0; h < 4; h++)
#pragma unroll
        for (int r = 0; r < 4; r++) acc[h][r] = 0ull;

    for (int kc = 0; kc < 64; kc++) {
        const int k0 = kc * 16;
        __syncthreads();
        // load 512 rows x 16 k (64B aligned segments)
#pragma unroll
        for (int it = 0; it < 8; it++) {
            int v = tid + 256 * it;          // 0..2047
            int row = v >> 2, qd = (v & 3) * 4;
            float4 d4 = *(const float4*)(Fbase + row * NF + k0 + qd);
            Fs[(qd + 0) * 516 + row] = d4.x;
            Fs[(qd + 1) * 516 + row] = d4.y;
            Fs[(qd + 2) * 516 + row] = d4.z;
            Fs[(qd + 3) * 516 + row] = d4.w;
        }
        ((float*)ps)[tid] = g_p[(b * NF + k0) * NH + tid];   // 256 contiguous
        __syncthreads();
#pragma unroll
        for (int kk = 0; kk < 16; kk++) {
            float4 fa = *(const float4*)&Fs[kk * 516 + r0];
            float4 fb = *(const float4*)&Fs[kk * 516 + r0 + 4];
            unsigned long long F2[4];
            F2[0] = pk2(fa.x, fa.y); F2[1] = pk2(fa.z, fa.w);
            F2[2] = pk2(fb.x, fb.y); F2[3] = pk2(fb.z, fb.w);
#pragma unroll
            for (int h = 0; h < 4; h++) {
                float pv = ps[kk][h0 + h];
                unsigned long long p2 = pk2(pv, pv);
                acc[h][0] = ffma2(F2[0], p2, acc[h][0]);
                acc[h][1] = ffma2(F2[1], p2, acc[h][1]);
                acc[h][2] = ffma2(F2[2], p2, acc[h][2]);
                acc[h][3] = ffma2(F2[3], p2, acc[h][3]);
            }
        }
    }
#pragma unroll
    for (int h = 0; h < 4; h++) {
        float o[8];
#pragma unroll
        for (int r = 0; r < 4; r++) upk2(acc[h][r], o[2 * r], o[2 * r + 1]);
        float* Lp = g_L + (b * NH + h0 + h) * NT + t0 + r0;
        *(float4*)Lp       = make_float4(o[0], o[1], o[2], o[3]);
        *(float4*)(Lp + 4) = make_float4(o[4], o[5], o[6], o[7]);
    }
}

// ---------------- softmax over t per (b,h), in place on g_L ----------------
__global__ void softmax_kernel() {
    __shared__ float xs[NT];
    __shared__ float red[256];
    const int bh = blockIdx.x, tid = threadIdx.x;
    float* Lp = g_L + bh * NT;
    float lmax = -1e30f;
    for (int i = tid; i < NT; i += 256) {
        float v = Lp[i];
        xs[i] = v;
        lmax = fmaxf(lmax, v);
    }
    red[tid] = lmax;
    __syncthreads();
    for (int s = 128; s > 0; s >>= 1) {
        if (tid < s) red[tid] = fmaxf(red[tid], red[tid + s]);
        __syncthreads();
    }
    float m = red[0];
    __syncthreads();
    float lsum = 0.f;
    for (int i = tid; i < NT; i += 256) {
        float e = __expf(xs[i] - m);
        xs[i] = e;
        lsum += e;
    }
    red[tid] = lsum;
    __syncthreads();
    for (int s = 128; s > 0; s >>= 1) {
        if (tid < s) red[tid] += red[tid + s];
        __syncthreads();
    }
    float inv = 1.f / red[0];
    for (int i = tid; i < NT; i += 256) Lp[i] = xs[i] * inv;
}

// ---------------- pass2: wp[b][c][h][f] = sum_{t in chunk c} A[b][h][t]*F[b][t][f]
// grid (8 t-chunks of 512, 32 b), 256 threads; thread tile 4 heads x 16 f
// f mapping segmented: f = seg*256 + fg*4 (conflict-free LDS, coalesced STG)
__global__ __launch_bounds__(256) void pass2_kernel(const float* __restrict__ F) {
    __shared__ __align__(16) float Fs[8 * NF];   // [t][f]
    __shared__ float As[8][16];                  // [t][h]
    const int b = blockIdx.y, c = blockIdx.x;
    const int tb = c * 512;
    const int tid = threadIdx.x;
    const int hg = tid >> 6, fg = tid & 63;
    const int h0 = hg * 4;

    unsigned long long acc[4][8];
#pragma unroll
    for (int h = 0; h < 4; h++)
#pragma unroll
        for (int r = 0; r < 8; r++) acc[h][r] = 0ull;

    for (int kc = 0; kc < 64; kc++) {
        const int t0 = tb + kc * 8;
        __syncthreads();
#pragma unroll
        for (int it = 0; it < 8; it++) {
            int v = tid + 256 * it;          // 0..2047
            int row = v >> 8, cq = (v & 255) * 4;
            *(float4*)&Fs[row * NF + cq] =
                *(const float4*)(F + (b * NT + t0 + row) * NF + cq);
        }
        if (tid < 128) {
            int hh = tid >> 3, kk = tid & 7;
            As[kk][hh] = g_L[(b * NH + hh) * NT + t0 + kk];
        }
        __syncthreads();
#pragma unroll
        for (int kk = 0; kk < 8; kk++) {
            unsigned long long F2[8];
#pragma unroll
            for (int seg = 0; seg < 4; seg++) {
                float4 fa = *(const float4*)&Fs[kk * NF + seg * 256 + fg * 4];
                F2[seg * 2]     = pk2(fa.x, fa.y);
                F2[seg * 2 + 1] = pk2(fa.z, fa.w);
            }
#pragma unroll
            for (int h = 0; h < 4; h++) {
                float av = As[kk][h0 + h];
                unsigned long long a2 = pk2(av, av);
#pragma unroll
                for (int r = 0; r < 8; r++) acc[h][r] = ffma2(F2[r], a2, acc[h][r]);
            }
        }
    }
#pragma unroll
    for (int h = 0; h < 4; h++) {
#pragma unroll
        for (int seg = 0; seg < 4; seg++) {
            float o0, o1, o2, o3;
            upk2(acc[h][seg * 2], o0, o1);
            upk2(acc[h][seg * 2 + 1], o2, o3);
            float* wpp = g_wp + ((b * 8 + c) * NH + h0 + h) * NF + seg * 256 + fg * 4;
            *(float4*)wpp = make_float4(o0, o1, o2, o3);
        }
    }
}

// w[b][h][f] = sum_c wp[b][c][h][f];  n = 524288, grid 2048 x 256
__global__ void combine_w_kernel() {
    int i = blockIdx.x * 256 + threadIdx.x;
    int b = i >> 14, hf = i & 16383;
    float s = 0.f;
#pragma unroll
    for (int c = 0; c < 8; c++) s += g_wp[(b * 8 + c) * (NH * NF) + hf];
    g_w[i] = s;
}

// op[fc][b][j] = sum_{f in 64-chunk fc} w[b][j/64][f] * Wv[f][j]
// grid (8 j-tiles, 16 f-chunks), 128 threads
__global__ void outpart_kernel(const float* __restrict__ Wv) {
    __shared__ float ws[32][2][64];
    const int jt = blockIdx.x, fc = blockIdx.y, tid = threadIdx.x;
    for (int i = tid; i < 32 * 2 * 64; i += 128) {
        int bb = i >> 7, hl = (i >> 6) & 1, fl = i & 63;
        ws[bb][hl][fl] = g_w[(bb * NH + jt * 2 + hl) * NF + fc * 64 + fl];
    }
    __syncthreads();
    const int j = jt * 128 + tid;
    const int hl = tid >> 6;
    float acc[32];
#pragma unroll
    for (int bb = 0; bb < 32; bb++) acc[bb] = 0.f;
    for (int fl = 0; fl < 64; fl++) {
        float wvv = Wv[(fc * 64 + fl) * NDM + j];
#pragma unroll
        for (int bb = 0; bb < 32; bb++) acc[bb] += ws[bb][hl][fl] * wvv;
    }
#pragma unroll
    for (int bb = 0; bb < 32; bb++) g_op[(fc * 32 + bb) * NDM + j] = acc[bb];
}

// ---------------- host launcher ----------------
extern "C" void kernel_launch(void* const* d_in, const int* in_sizes, int n_in,
                              void* d_out, int out_size) {
    const float* features = (const float*)d_in[0];
    const float* state    = (const float*)d_in[1];
    const float* Wq       = (const float*)d_in[2];
    const float* bq       = (const float*)d_in[3];
    const float* Wv       = (const float*)d_in[4];
    const float* bv       = (const float*)d_in[5];
    const float* Wd       = (const float*)d_in[6];
    const float* bd       = (const float*)d_in[7];
    float* out = (float*)d_out;

    void *p_qpart, *p_q, *p_op, *p_out, *p_fpart;
    cudaGetSymbolAddress(&p_qpart, g_qpart);
    cudaGetSymbolAddress(&p_q, g_q);
    cudaGetSymbolAddress(&p_op, g_op);
    cudaGetSymbolAddress(&p_out, g_out);
    cudaGetSymbolAddress(&p_fpart, g_fpart);

    // q = state @ Wq + bq
    gemv_part_kernel<<<dim3(8, 16), 128>>>(state, Wq, (float*)p_qpart);
    combine_kernel<<<128, 256>>>((const float*)p_qpart, bq, (float*)p_q);
    // p[b][f][h] (logit projection, scaled 1/8)
    pcalc_kernel<<<dim3(64, 4), 256>>>(Wv);
    // logits
    pass1_kernel<<<dim3(8, 32), 256>>>(features);
    // softmax (in place -> attention weights)
    softmax_kernel<<<NB * NH, 256>>>();
    // w = attn @ features (t-chunk partials, then reduce)
    pass2_kernel<<<dim3(8, 32), 256>>>(features);
    combine_w_kernel<<<2048, 256>>>();
    // out = w @ Wv + bv
    outpart_kernel<<<dim3(8, 16), 128>>>(Wv);
    combine_kernel<<<128, 256>>>((const float*)p_op, bv, (float*)p_out);
    // final = out @ Wd + bd
    gemv_part_kernel<<<dim3(8, 16), 128>>>((const float*)p_out, Wd, (float*)p_fpart);
    combine_kernel<<<128, 256>>>((const float*)p_fpart, bd, out);
    (void)in_sizes; (void)n_in; (void)out_size;
}

// round 4
// speedup vs baseline: 1.1989x; 1.1102x over previous
#include <cuda_runtime.h>

// Problem constants
#define NB   32
#define NT   4096
#define NF   1024     // F_IN
#define NH   16
#define NDEP 64
#define NDM  1024     // D
#define KS   4        // pass1 k-split factor
#define TC   16       // pass2 t-chunks

// ---------------- scratch (device globals; no allocation) ----------------
__device__ float g_qpart[16 * NB * NDM];         // q GEMV k-split partials
__device__ float g_q[NB * NDM];                  // q = state@Wq + bq
__device__ float g_p[NB * NF * NH];              // p[b][f][h], scaled by 1/8
__device__ float g_Lp[KS * NB * NH * NT];        // logit k-split partials
__device__ float g_L[NB * NH * NT];              // attention weights
__device__ float g_wp[NB * TC * NH * NF];        // pass2 t-chunk partials
__device__ float g_w[NB * NH * NF];              // w[b][h][f]
__device__ float g_op[16 * NB * NDM];            // out f-split partials
__device__ float g_out[NB * NDM];                // out + bv
__device__ float g_fpart[16 * NB * NDM];         // final GEMV partials

// ---------------- f32x2 packed helpers ----------------
__device__ __forceinline__ unsigned long long pk2(float lo, float hi) {
    unsigned long long r;
    asm("mov.b64 %0, {%1, %2};" : "=l"(r) : "f"(lo), "f"(hi));
    return r;
}
__device__ __forceinline__ unsigned long long ffma2(unsigned long long a,
                                                    unsigned long long b,
                                                    unsigned long long c) {
    unsigned long long d;
    asm("fma.rn.f32x2 %0, %1, %2, %3;" : "=l"(d) : "l"(a), "l"(b), "l"(c));
    return d;
}
__device__ __forceinline__ void upk2(unsigned long long v, float& lo, float& hi) {
    asm("mov.b64 {%0, %1}, %2;" : "=f"(lo), "=f"(hi) : "l"(v));
}

// ---------------- generic 32-batch GEMV, 16-way k-split partials ----------
__global__ void gemv_part_kernel(const float* __restrict__ X,
                                 const float* __restrict__ W,
                                 float* __restrict__ part) {
    __shared__ float xs[32][64];
    const int jt = blockIdx.x, kc = blockIdx.y, tid = threadIdx.x;
    for (int i = tid; i < 32 * 64; i += 128) {
        int bb = i >> 6, kl = i & 63;
        xs[bb][kl] = X[bb * NDM + kc * 64 + kl];
    }
    __syncthreads();
    const int j = jt * 128 + tid;
    float acc[32];
#pragma unroll
    for (int bb = 0; bb < 32; bb++) acc[bb] = 0.f;
    for (int kl = 0; kl < 64; kl++) {
        float wv = W[(kc * 64 + kl) * NDM + j];
#pragma unroll
        for (int bb = 0; bb < 32; bb++) acc[bb] += xs[bb][kl] * wv;
    }
#pragma unroll
    for (int bb = 0; bb < 32; bb++) part[(kc * 32 + bb) * NDM + j] = acc[bb];
}

// out[i] = bias[i%1024] + sum_{c<16} part[c][i];  n = 32768
__global__ void combine_kernel(const float* __restrict__ part,
                               const float* __restrict__ bias,
                               float* __restrict__ out) {
    int i = blockIdx.x * 256 + threadIdx.x;
    float s = bias[i & (NDM - 1)];
#pragma unroll
    for (int c = 0; c < 16; c++) s += part[c * (32 * NDM) + i];
    out[i] = s;
}

// ---------------- p[b][f][h] = (1/8) sum_d Wv[f][h*64+d] * q[b][h*64+d] ----
__global__ void pcalc_kernel(const float* __restrict__ Wv) {
    __shared__ float qs[8][NDM];
    const int ft = blockIdx.x, bg = blockIdx.y, tid = threadIdx.x;
    for (int i = tid; i < 8 * NDM; i += 256)
        qs[i >> 10][i & 1023] = g_q[(bg * 8 + (i >> 10)) * NDM + (i & 1023)];
    __syncthreads();
    const int h = tid >> 4, fl = tid & 15;
    const int f = ft * 16 + fl;
    float acc[8];
#pragma unroll
    for (int bb = 0; bb < 8; bb++) acc[bb] = 0.f;
    for (int d = 0; d < NDEP; d++) {
        float wv = Wv[f * NDM + h * NDEP + d];
#pragma unroll
        for (int bb = 0; bb < 8; bb++) acc[bb] += wv * qs[bb][h * NDEP + d];
    }
#pragma unroll
    for (int bb = 0; bb < 8; bb++)
        g_p[((bg * 8 + bb) * NF + f) * NH + h] = acc[bb] * 0.125f;
}

// ---------------- pass1: Lp[kz][b][h][t] = sum_{f in kz-range} F[b][t][f]*p[b][f][h]
// grid (8 t-tiles of 512, 32 b, 4 kz), 128 threads; tile 8 rows x 8 heads
__global__ __launch_bounds__(128, 4) void pass1_kernel(const float* __restrict__ F) {
    __shared__ __align__(16) float Fs[16 * 516];          // [k][row], pad 4
    __shared__ __align__(16) unsigned long long ps2[256]; // [k][h] broadcast pairs
    const int b = blockIdx.y, t0 = blockIdx.x * 512, kz = blockIdx.z;
    const int kbase = kz * (NF / KS);
    const int tid = threadIdx.x;
    const int hg = tid >> 6, rg = tid & 63;
    const int r0 = rg * 8, h0 = hg * 8;
    const float* Fbase = F + (b * NT + t0) * NF;

    unsigned long long acc[8][4];
#pragma unroll
    for (int h = 0; h < 8; h++)
#pragma unroll
        for (int r = 0; r < 4; r++) acc[h][r] = 0ull;

    for (int kc = 0; kc < 16; kc++) {
        const int k0 = kbase + kc * 16;
        __syncthreads();
#pragma unroll
        for (int it = 0; it < 16; it++) {
            int v = tid + 128 * it;          // 0..2047
            int row = v >> 2, qd = (v & 3) * 4;
            float4 d4 = *(const float4*)(Fbase + row * NF + k0 + qd);
            Fs[(qd + 0) * 516 + row] = d4.x;
            Fs[(qd + 1) * 516 + row] = d4.y;
            Fs[(qd + 2) * 516 + row] = d4.z;
            Fs[(qd + 3) * 516 + row] = d4.w;
        }
        {
            float v0 = g_p[(b * NF + k0) * NH + tid];
            float v1 = g_p[(b * NF + k0) * NH + tid + 128];
            ps2[tid] = pk2(v0, v0);
            ps2[tid + 128] = pk2(v1, v1);
        }
        __syncthreads();
#pragma unroll
        for (int kk = 0; kk < 16; kk++) {
            float4 fa = *(const float4*)&Fs[kk * 516 + r0];
            float4 fb = *(const float4*)&Fs[kk * 516 + r0 + 4];
            unsigned long long F2[4];
            F2[0] = pk2(fa.x, fa.y); F2[1] = pk2(fa.z, fa.w);
            F2[2] = pk2(fb.x, fb.y); F2[3] = pk2(fb.z, fb.w);
#pragma unroll
            for (int h = 0; h < 8; h++) {
                unsigned long long p2 = ps2[kk * 16 + h0 + h];
                acc[h][0] = ffma2(F2[0], p2, acc[h][0]);
                acc[h][1] = ffma2(F2[1], p2, acc[h][1]);
                acc[h][2] = ffma2(F2[2], p2, acc[h][2]);
                acc[h][3] = ffma2(F2[3], p2, acc[h][3]);
            }
        }
    }
#pragma unroll
    for (int h = 0; h < 8; h++) {
        float o[8];
#pragma unroll
        for (int r = 0; r < 4; r++) upk2(acc[h][r], o[2 * r], o[2 * r + 1]);
        float* Lp = g_Lp + ((kz * NB + b) * NH + h0 + h) * NT + t0 + r0;
        *(float4*)Lp       = make_float4(o[0], o[1], o[2], o[3]);
        *(float4*)(Lp + 4) = make_float4(o[4], o[5], o[6], o[7]);
    }
}

// ---------------- softmax: sum 4 k-split partials, softmax over t, write g_L
__global__ void softmax_kernel() {
    __shared__ float xs[NT];
    __shared__ float red[256];
    const int bh = blockIdx.x, tid = threadIdx.x;
    const float* L0 = g_Lp + bh * NT;
    float* Lo = g_L + bh * NT;
    float lmax = -1e30f;
    for (int i = tid; i < NT; i += 256) {
        float v = L0[i] + L0[NB * NH * NT + i] + L0[2 * NB * NH * NT + i]
                + L0[3 * NB * NH * NT + i];
        xs[i] = v;
        lmax = fmaxf(lmax, v);
    }
    red[tid] = lmax;
    __syncthreads();
    for (int s = 128; s > 0; s >>= 1) {
        if (tid < s) red[tid] = fmaxf(red[tid], red[tid + s]);
        __syncthreads();
    }
    float m = red[0];
    __syncthreads();
    float lsum = 0.f;
    for (int i = tid; i < NT; i += 256) {
        float e = __expf(xs[i] - m);
        xs[i] = e;
        lsum += e;
    }
    red[tid] = lsum;
    __syncthreads();
    for (int s = 128; s > 0; s >>= 1) {
        if (tid < s) red[tid] += red[tid + s];
        __syncthreads();
    }
    float inv = 1.f / red[0];
    for (int i = tid; i < NT; i += 256) Lo[i] = xs[i] * inv;
}

// ---------------- pass2: wp[b][c][h][f] = sum_{t in 256-chunk c} A[b][h][t]*F[b][t][f]
// grid (16 t-chunks, 32 b), 256 threads; thread tile 8 heads x 8 f (2 segs of 4)
__global__ __launch_bounds__(256, 2) void pass2_kernel(const float* __restrict__ F) {
    __shared__ __align__(16) float Fs[8 * NF];            // [t][f]
    __shared__ __align__(16) unsigned long long As2[128]; // [t][h] broadcast pairs
    const int b = blockIdx.y, c = blockIdx.x;
    const int tb = c * 256;
    const int tid = threadIdx.x;
    const int hg = tid >> 7, fg = tid & 127;
    const int h0 = hg * 8;

    unsigned long long acc[8][4];
#pragma unroll
    for (int h = 0; h < 8; h++)
#pragma unroll
        for (int r = 0; r < 4; r++) acc[h][r] = 0ull;

    for (int kc = 0; kc < 32; kc++) {
        const int t0 = tb + kc * 8;
        __syncthreads();
#pragma unroll
        for (int it = 0; it < 8; it++) {
            int v = tid + 256 * it;          // 0..2047
            int row = v >> 8, cq = (v & 255) * 4;
            *(float4*)&Fs[row * NF + cq] =
                *(const float4*)(F + (b * NT + t0 + row) * NF + cq);
        }
        if (tid < 128) {
            int kk = tid >> 4, hh = tid & 15;
            float av = g_L[(b * NH + hh) * NT + t0 + kk];
            As2[tid] = pk2(av, av);
        }
        __syncthreads();
#pragma unroll
        for (int kk = 0; kk < 8; kk++) {
            unsigned long long F2[4];
            float4 fa = *(const float4*)&Fs[kk * NF + fg * 4];
            float4 fb = *(const float4*)&Fs[kk * NF + 512 + fg * 4];
            F2[0] = pk2(fa.x, fa.y); F2[1] = pk2(fa.z, fa.w);
            F2[2] = pk2(fb.x, fb.y); F2[3] = pk2(fb.z, fb.w);
#pragma unroll
            for (int h = 0; h < 8; h++) {
                unsigned long long a2 = As2[kk * 16 + h0 + h];
#pragma unroll
                for (int r = 0; r < 4; r++) acc[h][r] = ffma2(F2[r], a2, acc[h][r]);
            }
        }
    }
#pragma unroll
    for (int h = 0; h < 8; h++) {
#pragma unroll
        for (int seg = 0; seg < 2; seg++) {
            float o0, o1, o2, o3;
            upk2(acc[h][seg * 2], o0, o1);
            upk2(acc[h][seg * 2 + 1], o2, o3);
            float* wpp = g_wp + ((b * TC + c) * NH + h0 + h) * NF + seg * 512 + fg * 4;
            *(float4*)wpp = make_float4(o0, o1, o2, o3);
        }
    }
}

// w[b][h][f] = sum_c wp[b][c][h][f];  n = 524288, grid 2048 x 256
__global__ void combine_w_kernel() {
    int i = blockIdx.x * 256 + threadIdx.x;
    int b = i >> 14, hf = i & 16383;
    float s = 0.f;
#pragma unroll
    for (int c = 0; c < TC; c++) s += g_wp[(b * TC + c) * (NH * NF) + hf];
    g_w[i] = s;
}

// op[fc][b][j] = sum_{f in 64-chunk fc} w[b][j/64][f] * Wv[f][j]
__global__ void outpart_kernel(const float* __restrict__ Wv) {
    __shared__ float ws[32][2][64];
    const int jt = blockIdx.x, fc = blockIdx.y, tid = threadIdx.x;
    for (int i = tid; i < 32 * 2 * 64; i += 128) {
        int bb = i >> 7, hl = (i >> 6) & 1, fl = i & 63;
        ws[bb][hl][fl] = g_w[(bb * NH + jt * 2 + hl) * NF + fc * 64 + fl];
    }
    __syncthreads();
    const int j = jt * 128 + tid;
    const int hl = tid >> 6;
    float acc[32];
#pragma unroll
    for (int bb = 0; bb < 32; bb++) acc[bb] = 0.f;
    for (int fl = 0; fl < 64; fl++) {
        float wvv = Wv[(fc * 64 + fl) * NDM + j];
#pragma unroll
        for (int bb = 0; bb < 32; bb++) acc[bb] += ws[bb][hl][fl] * wvv;
    }
#pragma unroll
    for (int bb = 0; bb < 32; bb++) g_op[(fc * 32 + bb) * NDM + j] = acc[bb];
}

// ---------------- host launcher ----------------
extern "C" void kernel_launch(void* const* d_in, const int* in_sizes, int n_in,
                              void* d_out, int out_size) {
    const float* features = (const float*)d_in[0];
    const float* state    = (const float*)d_in[1];
    const float* Wq       = (const float*)d_in[2];
    const float* bq       = (const float*)d_in[3];
    const float* Wv       = (const float*)d_in[4];
    const float* bv       = (const float*)d_in[5];
    const float* Wd       = (const float*)d_in[6];
    const float* bd       = (const float*)d_in[7];
    float* out = (float*)d_out;

    void *p_qpart, *p_q, *p_op, *p_out, *p_fpart;
    cudaGetSymbolAddress(&p_qpart, g_qpart);
    cudaGetSymbolAddress(&p_q, g_q);
    cudaGetSymbolAddress(&p_op, g_op);
    cudaGetSymbolAddress(&p_out, g_out);
    cudaGetSymbolAddress(&p_fpart, g_fpart);

    // q = state @ Wq + bq
    gemv_part_kernel<<<dim3(8, 16), 128>>>(state, Wq, (float*)p_qpart);
    combine_kernel<<<128, 256>>>((const float*)p_qpart, bq, (float*)p_q);
    // p[b][f][h] (logit projection, scaled 1/8)
    pcalc_kernel<<<dim3(64, 4), 256>>>(Wv);
    // logit partials (k-split x4)
    pass1_kernel<<<dim3(8, 32, KS), 128>>>(features);
    // softmax (sums partials -> attention weights)
    softmax_kernel<<<NB * NH, 256>>>();
    // w = attn @ features (t-chunk partials, then reduce)
    pass2_kernel<<<dim3(TC, 32), 256>>>(features);
    combine_w_kernel<<<2048, 256>>>();
    // out = w @ Wv + bv
    outpart_kernel<<<dim3(8, 16), 128>>>(Wv);
    combine_kernel<<<128, 256>>>((const float*)p_op, bv, (float*)p_out);
    // final = out @ Wd + bd
    gemv_part_kernel<<<dim3(8, 16), 128>>>((const float*)p_out, Wd, (float*)p_fpart);
    combine_kernel<<<128, 256>>>((const float*)p_fpart, bd, out);
    (void)in_sizes; (void)n_in; (void)out_size;
}

// round 5
// speedup vs baseline: 1.5206x; 1.2683x over previous
#include <cuda_runtime.h>

// Problem constants
#define NB   32
#define NT   4096
#define NF   1024     // F_IN
#define NH   16
#define NDEP 64
#define NDM  1024     // D
#define KS   4        // pass1 k-split factor
#define TC   16       // pass2 t-chunks

typedef unsigned long long ull;

// ---------------- scratch (device globals; no allocation) ----------------
__device__ float g_qpart[16 * NB * NDM];
__device__ float g_q[NB * NDM];
__device__ ull   g_p2[NB * 512 * NH];            // (p[2P][h], p[2P+1][h]) pairs
__device__ float g_Lp[KS * NB * NH * NT];        // logit k-split partials
__device__ ull   g_A2[NB * NT * NH];             // attn dup pairs [b][t][h]
__device__ float g_wp[NB * TC * NH * NF];        // pass2 t-chunk partials
__device__ float g_w[NB * NH * NF];
__device__ float g_op[16 * NB * NDM];
__device__ float g_out[NB * NDM];
__device__ float g_fpart[16 * NB * NDM];

// ---------------- helpers ----------------
__device__ __forceinline__ ull pk2(float lo, float hi) {
    ull r;
    asm("mov.b64 %0, {%1, %2};" : "=l"(r) : "f"(lo), "f"(hi));
    return r;
}
__device__ __forceinline__ ull ffma2(ull a, ull b, ull c) {
    ull d;
    asm("fma.rn.f32x2 %0, %1, %2, %3;" : "=l"(d) : "l"(a), "l"(b), "l"(c));
    return d;
}
__device__ __forceinline__ void upk2(ull v, float& lo, float& hi) {
    asm("mov.b64 {%0, %1}, %2;" : "=f"(lo), "=f"(hi) : "l"(v));
}
__device__ __forceinline__ void cpa16(unsigned dst, const void* src) {
    asm volatile("cp.async.cg.shared.global [%0], [%1], 16;" :: "r"(dst), "l"(src));
}
__device__ __forceinline__ void cpacommit() {
    asm volatile("cp.async.commit_group;" ::: "memory");
}
__device__ __forceinline__ void cpawait0() {
    asm volatile("cp.async.wait_group 0;" ::: "memory");
}

// ---------------- generic 32-batch GEMV, 16-way k-split partials ----------
__global__ void gemv_part_kernel(const float* __restrict__ X,
                                 const float* __restrict__ W,
                                 float* __restrict__ part) {
    __shared__ float xs[32][64];
    const int jt = blockIdx.x, kc = blockIdx.y, tid = threadIdx.x;
    for (int i = tid; i < 32 * 64; i += 128) {
        int bb = i >> 6, kl = i & 63;
        xs[bb][kl] = X[bb * NDM + kc * 64 + kl];
    }
    __syncthreads();
    const int j = jt * 128 + tid;
    float acc[32];
#pragma unroll
    for (int bb = 0; bb < 32; bb++) acc[bb] = 0.f;
    for (int kl = 0; kl < 64; kl++) {
        float wv = W[(kc * 64 + kl) * NDM + j];
#pragma unroll
        for (int bb = 0; bb < 32; bb++) acc[bb] += xs[bb][kl] * wv;
    }
#pragma unroll
    for (int bb = 0; bb < 32; bb++) part[(kc * 32 + bb) * NDM + j] = acc[bb];
}

__global__ void combine_kernel(const float* __restrict__ part,
                               const float* __restrict__ bias,
                               float* __restrict__ out) {
    int i = blockIdx.x * 256 + threadIdx.x;
    float s = bias[i & (NDM - 1)];
#pragma unroll
    for (int c = 0; c < 16; c++) s += part[c * (32 * NDM) + i];
    out[i] = s;
}

// ---------------- p2[b][P][h] = (1/8)*(sum_d Wv[2P][..]q, sum_d Wv[2P+1][..]q)
__global__ void pcalc_kernel(const float* __restrict__ Wv) {
    __shared__ float qs[8][NDM];
    const int ft = blockIdx.x, bg = blockIdx.y, tid = threadIdx.x;
    for (int i = tid; i < 8 * NDM; i += 256)
        qs[i >> 10][i & 1023] = g_q[(bg * 8 + (i >> 10)) * NDM + (i & 1023)];
    __syncthreads();
    const int h = tid >> 4, fl = tid & 15;
    const int f = ft * 16 + fl;
    float acc[8];
#pragma unroll
    for (int bb = 0; bb < 8; bb++) acc[bb] = 0.f;
    for (int d = 0; d < NDEP; d++) {
        float wv = Wv[f * NDM + h * NDEP + d];
#pragma unroll
        for (int bb = 0; bb < 8; bb++) acc[bb] += wv * qs[bb][h * NDEP + d];
    }
    float* p2f = (float*)g_p2;
#pragma unroll
    for (int bb = 0; bb < 8; bb++) {
        int b = bg * 8 + bb;
        p2f[(((b * 512) + (f >> 1)) * NH + h) * 2 + (f & 1)] = acc[bb] * 0.125f;
    }
}

// ---------------- pass1: Lp[kz][b][h][t] = sum_{k in kz-range} F[t][k]*p[k][h]
// grid (8 t-tiles of 512, 32 b, 4 kz), 128 threads; thread 4 rows x 8 heads
// smem: Fs double-buffer 2x[256 rows][8 f4] swizzled (64KB) + p2s 128x16 ull (16KB)
__global__ __launch_bounds__(128) void pass1_kernel(const float* __restrict__ F) {
    extern __shared__ __align__(16) char sm1[];
    float4* Fs = (float4*)sm1;                        // 2 * 2048 float4
    ull* p2s = (ull*)(sm1 + 2 * 2048 * 16);           // 2048 ull
    const unsigned fs_base = (unsigned)__cvta_generic_to_shared(Fs);
    const unsigned p2_base = (unsigned)__cvta_generic_to_shared(p2s);

    const int b = blockIdx.y, kz = blockIdx.z;
    const int tbase = blockIdx.x * 512;
    const int tid = threadIdx.x;
    const int hg = tid >> 6, h0 = hg * 8, rg = tid & 63;
    const int r0 = rg * 4;
    const int keyc = rg & 7;                          // swizzle key (constant)

    // preload p2 slice (16KB) + first F chunk, one commit group
    {
        const float4* src = (const float4*)(g_p2 + (b * 512 + kz * 128) * NH);
#pragma unroll
        for (int it = 0; it < 8; it++) {
            int i = tid + 128 * it;
            cpa16(p2_base + i * 16, src + i);
        }
        const float* base = F + (b * NT + tbase) * NF + kz * 256;
#pragma unroll
        for (int it = 0; it < 16; it++) {
            int i = tid + 128 * it;
            int row = i >> 3, c = i & 7;
            cpa16(fs_base + (row * 8 + (c ^ ((row >> 2) & 7))) * 16,
                  base + row * NF + c * 4);
        }
        cpacommit();
    }

    ull acc[4][8];
#pragma unroll
    for (int r = 0; r < 4; r++)
#pragma unroll
        for (int hh = 0; hh < 8; hh++) acc[r][hh] = 0ull;

    for (int s = 0; s < 16; s++) {
        cpawait0();
        __syncthreads();
        if (s < 15) {
            int sn = s + 1;
            int half = sn >> 3, kc = sn & 7;
            const float* base = F + (b * NT + tbase + half * 256) * NF
                              + kz * 256 + kc * 32;
            unsigned dstb = fs_base + (sn & 1) * 2048 * 16;
#pragma unroll
            for (int it = 0; it < 16; it++) {
                int i = tid + 128 * it;
                int row = i >> 3, c = i & 7;
                cpa16(dstb + (row * 8 + (c ^ ((row >> 2) & 7))) * 16,
                      base + row * NF + c * 4);
            }
            cpacommit();
        }
        const float4* buf = Fs + (s & 1) * 2048;
        const int kc = s & 7;
#pragma unroll
        for (int c = 0; c < 8; c++) {
            // p2 pairs for k-pairs P = kc*16 + c*2 + {0,1}, heads h0..h0+7
            ull pp0[8], pp1[8];
            {
                const ulonglong2* q0 = (const ulonglong2*)(p2s + (kc * 16 + c * 2) * NH + h0);
                const ulonglong2* q1 = (const ulonglong2*)(p2s + (kc * 16 + c * 2 + 1) * NH + h0);
#pragma unroll
                for (int q = 0; q < 4; q++) {
                    ulonglong2 a = q0[q]; pp0[2 * q] = a.x; pp0[2 * q + 1] = a.y;
                    ulonglong2 bq = q1[q]; pp1[2 * q] = bq.x; pp1[2 * q + 1] = bq.y;
                }
            }
#pragma unroll
            for (int r = 0; r < 4; r++) {
                int row = r0 + r;
                ulonglong2 u = *(const ulonglong2*)(buf + row * 8 + (c ^ keyc));
#pragma unroll
                for (int hh = 0; hh < 8; hh++) {
                    acc[r][hh] = ffma2(u.x, pp0[hh], acc[r][hh]);
                    acc[r][hh] = ffma2(u.y, pp1[hh], acc[r][hh]);
                }
            }
        }
        if (kc == 7) {
            int half = s >> 3;
#pragma unroll
            for (int hh = 0; hh < 8; hh++) {
                float4 o;
                float lo, hi;
                upk2(acc[0][hh], lo, hi); o.x = lo + hi;
                upk2(acc[1][hh], lo, hi); o.y = lo + hi;
                upk2(acc[2][hh], lo, hi); o.z = lo + hi;
                upk2(acc[3][hh], lo, hi); o.w = lo + hi;
                *(float4*)(g_Lp + ((kz * NB + b) * NH + h0 + hh) * NT
                           + tbase + half * 256 + r0) = o;
            }
#pragma unroll
            for (int r = 0; r < 4; r++)
#pragma unroll
                for (int hh = 0; hh < 8; hh++) acc[r][hh] = 0ull;
        }
    }
}

// ---------------- softmax: sum KS partials, softmax, write dup pairs g_A2
__global__ void softmax_kernel() {
    __shared__ float xs[NT];
    __shared__ float red[256];
    const int bh = blockIdx.x, tid = threadIdx.x;
    const int b = bh >> 4, h = bh & 15;
    const float* L0 = g_Lp + bh * NT;
    float lmax = -1e30f;
    for (int i = tid; i < NT; i += 256) {
        float v = L0[i] + L0[NB * NH * NT + i] + L0[2 * NB * NH * NT + i]
                + L0[3 * NB * NH * NT + i];
        xs[i] = v;
        lmax = fmaxf(lmax, v);
    }
    red[tid] = lmax;
    __syncthreads();
    for (int s = 128; s > 0; s >>= 1) {
        if (tid < s) red[tid] = fmaxf(red[tid], red[tid + s]);
        __syncthreads();
    }
    float m = red[0];
    __syncthreads();
    float lsum = 0.f;
    for (int i = tid; i < NT; i += 256) {
        float e = __expf(xs[i] - m);
        xs[i] = e;
        lsum += e;
    }
    red[tid] = lsum;
    __syncthreads();
    for (int s = 128; s > 0; s >>= 1) {
        if (tid < s) red[tid] += red[tid + s];
        __syncthreads();
    }
    float inv = 1.f / red[0];
    for (int i = tid; i < NT; i += 256) {
        float a = xs[i] * inv;
        g_A2[(b * NT + i) * NH + h] = pk2(a, a);
    }
}

// ---------------- pass2: wp[b][c][h][f] = sum_{t in 256-chunk} A[h][t]*F[t][f]
// grid (16 t-chunks, 32 b), 256 threads; thread 8 heads x 8 f; cp.async pipeline
__global__ __launch_bounds__(256) void pass2_kernel(const float* __restrict__ F) {
    extern __shared__ __align__(16) char sm2[];
    float4* Fs = (float4*)sm2;                        // 2 * 2048 float4 (8 rows x 1024)
    ull* As = (ull*)(sm2 + 2 * 2048 * 16);            // 2 * 128 ull
    const unsigned fs_base = (unsigned)__cvta_generic_to_shared(Fs);
    const unsigned as_base = (unsigned)__cvta_generic_to_shared(As);

    const int b = blockIdx.y, cblk = blockIdx.x;
    const int tb = cblk * 256;
    const int tid = threadIdx.x;
    const int hg = tid >> 7, h0 = hg * 8, fg = tid & 127;

    // prefetch sub-chunk 0
    {
        const float* base = F + (b * NT + tb) * NF;
#pragma unroll
        for (int it = 0; it < 8; it++) {
            int i = tid + 256 * it;
            int row = i >> 8, c = i & 255;
            cpa16(fs_base + (row * 256 + c) * 16, base + row * NF + c * 4);
        }
        if (tid < 64) {
            const float4* asrc = (const float4*)(g_A2 + (b * NT + tb) * NH);
            cpa16(as_base + tid * 16, asrc + tid);
        }
        cpacommit();
    }

    ull acc[8][4];
#pragma unroll
    for (int hh = 0; hh < 8; hh++)
#pragma unroll
        for (int r = 0; r < 4; r++) acc[hh][r] = 0ull;

    for (int s = 0; s < 32; s++) {
        cpawait0();
        __syncthreads();
        if (s < 31) {
            int t0 = tb + (s + 1) * 8;
            const float* base = F + (b * NT + t0) * NF;
            unsigned dstb = fs_base + ((s + 1) & 1) * 2048 * 16;
#pragma unroll
            for (int it = 0; it < 8; it++) {
                int i = tid + 256 * it;
                int row = i >> 8, c = i & 255;
                cpa16(dstb + (row * 256 + c) * 16, base + row * NF + c * 4);
            }
            if (tid < 64) {
                const float4* asrc = (const float4*)(g_A2 + (b * NT + t0) * NH);
                cpa16(as_base + ((s + 1) & 1) * 128 * 8 + tid * 16, asrc + tid);
            }
            cpacommit();
        }
        const float4* buf = Fs + (s & 1) * 2048;
        const ull* abuf = As + (s & 1) * 128;
#pragma unroll
        for (int kk = 0; kk < 8; kk++) {
            ull pp[8];
            {
                const ulonglong2* q = (const ulonglong2*)(abuf + kk * NH + h0);
#pragma unroll
                for (int qi = 0; qi < 4; qi++) {
                    ulonglong2 a = q[qi];
                    pp[2 * qi] = a.x; pp[2 * qi + 1] = a.y;
                }
            }
            ulonglong2 ua = *(const ulonglong2*)(buf + kk * 256 + fg);
            ulonglong2 ub = *(const ulonglong2*)(buf + kk * 256 + 128 + fg);
#pragma unroll
            for (int hh = 0; hh < 8; hh++) {
                acc[hh][0] = ffma2(ua.x, pp[hh], acc[hh][0]);
                acc[hh][1] = ffma2(ua.y, pp[hh], acc[hh][1]);
                acc[hh][2] = ffma2(ub.x, pp[hh], acc[hh][2]);
                acc[hh][3] = ffma2(ub.y, pp[hh], acc[hh][3]);
            }
        }
    }
#pragma unroll
    for (int hh = 0; hh < 8; hh++) {
        float o0, o1, o2, o3;
        float* wpp = g_wp + ((b * TC + cblk) * NH + h0 + hh) * NF;
        upk2(acc[hh][0], o0, o1); upk2(acc[hh][1], o2, o3);
        *(float4*)(wpp + fg * 4) = make_float4(o0, o1, o2, o3);
        upk2(acc[hh][2], o0, o1); upk2(acc[hh][3], o2, o3);
        *(float4*)(wpp + 512 + fg * 4) = make_float4(o0, o1, o2, o3);
    }
}

// w[b][h][f] = sum_c wp[b][c][h][f]
__global__ void combine_w_kernel() {
    int i = blockIdx.x * 256 + threadIdx.x;
    int b = i >> 14, hf = i & 16383;
    float s = 0.f;
#pragma unroll
    for (int c = 0; c < TC; c++) s += g_wp[(b * TC + c) * (NH * NF) + hf];
    g_w[i] = s;
}

// op[fc][b][j] = sum_{f in 64-chunk fc} w[b][j/64][f] * Wv[f][j]
__global__ void outpart_kernel(const float* __restrict__ Wv) {
    __shared__ float ws[32][2][64];
    const int jt = blockIdx.x, fc = blockIdx.y, tid = threadIdx.x;
    for (int i = tid; i < 32 * 2 * 64; i += 128) {
        int bb = i >> 7, hl = (i >> 6) & 1, fl = i & 63;
        ws[bb][hl][fl] = g_w[(bb * NH + jt * 2 + hl) * NF + fc * 64 + fl];
    }
    __syncthreads();
    const int j = jt * 128 + tid;
    const int hl = tid >> 6;
    float acc[32];
#pragma unroll
    for (int bb = 0; bb < 32; bb++) acc[bb] = 0.f;
    for (int fl = 0; fl < 64; fl++) {
        float wvv = Wv[(fc * 64 + fl) * NDM + j];
#pragma unroll
        for (int bb = 0; bb < 32; bb++) acc[bb] += ws[bb][hl][fl] * wvv;
    }
#pragma unroll
    for (int bb = 0; bb < 32; bb++) g_op[(fc * 32 + bb) * NDM + j] = acc[bb];
}

// ---------------- host launcher ----------------
extern "C" void kernel_launch(void* const* d_in, const int* in_sizes, int n_in,
                              void* d_out, int out_size) {
    const float* features = (const float*)d_in[0];
    const float* state    = (const float*)d_in[1];
    const float* Wq       = (const float*)d_in[2];
    const float* bq       = (const float*)d_in[3];
    const float* Wv       = (const float*)d_in[4];
    const float* bv       = (const float*)d_in[5];
    const float* Wd       = (const float*)d_in[6];
    const float* bd       = (const float*)d_in[7];
    float* out = (float*)d_out;

    void *p_qpart, *p_op, *p_out, *p_fpart;
    cudaGetSymbolAddress(&p_qpart, g_qpart);
    cudaGetSymbolAddress(&p_op, g_op);
    cudaGetSymbolAddress(&p_out, g_out);
    cudaGetSymbolAddress(&p_fpart, g_fpart);
    void* p_q; cudaGetSymbolAddress(&p_q, g_q);

    const int SM1 = 2 * 2048 * 16 + 2048 * 8;   // 81920
    const int SM2 = 2 * 2048 * 16 + 2 * 128 * 8; // 67584
    static int cfg_done = 0;
    if (!cfg_done) {
        cudaFuncSetAttribute(pass1_kernel,
            cudaFuncAttributeMaxDynamicSharedMemorySize, SM1);
        cudaFuncSetAttribute(pass2_kernel,
            cudaFuncAttributeMaxDynamicSharedMemorySize, SM2);
        cfg_done = 1;
    }

    // q = state @ Wq + bq
    gemv_part_kernel<<<dim3(8, 16), 128>>>(state, Wq, (float*)p_qpart);
    combine_kernel<<<128, 256>>>((const float*)p_qpart, bq, (float*)p_q);
    // p2 pairs
    pcalc_kernel<<<dim3(64, 4), 256>>>(Wv);
    // logit partials
    pass1_kernel<<<dim3(8, 32, KS), 128, SM1>>>(features);
    // softmax -> attn dup pairs
    softmax_kernel<<<NB * NH, 256>>>();
    // w = attn @ features
    pass2_kernel<<<dim3(TC, 32), 256, SM2>>>(features);
    combine_w_kernel<<<2048, 256>>>();
    // out = w @ Wv + bv
    outpart_kernel<<<dim3(8, 16), 128>>>(Wv);
    combine_kernel<<<128, 256>>>((const float*)p_op, bv, (float*)p_out);
    // final = out @ Wd + bd
    gemv_part_kernel<<<dim3(8, 16), 128>>>((const float*)p_out, Wd, (float*)p_fpart);
    combine_kernel<<<128, 256>>>((const float*)p_fpart, bd, out);
    (void)in_sizes; (void)n_in; (void)out_size;
}